// round 3
// baseline (speedup 1.0000x reference)
#include <cuda_runtime.h>
#include <math.h>

#define S 512
#define T 512
#define CM 64
#define CZ 128
#define H 8
#define D 32
#define HD 256

// Scratch (device globals: allocation-free rule)
__device__ float g_v[(size_t)S*T*HD];   // v[s][j][h*D+d]
__device__ float g_g[(size_t)S*T*HD];   // g[s][i][h*D+d] (sigmoid-gated)
__device__ float g_w[(size_t)T*H*T];    // b/w [i][h][j]  (softmax over j, contiguous)
__device__ float g_o[(size_t)S*T*HD];   // o[s][i][h*D+d]

// ---------------------------------------------------------------------------
// K1: LayerNorm(m) fused with v = mn@Wm and g = sigmoid(mn@Wg).
// 8 rows per block (one per warp for the LN), 256 threads = one output column
// of the 256-wide projection each; Wm/Wg loads amortized over the 8 rows.
// ---------------------------------------------------------------------------
__global__ void __launch_bounds__(256) k_ln_m_vg(
    const float* __restrict__ m,
    const float* __restrict__ lw, const float* __restrict__ lb,
    const float* __restrict__ Wm, const float* __restrict__ Wg)
{
    __shared__ float mn[8][CM];
    const int tid  = threadIdx.x;
    const int warp = tid >> 5, lane = tid & 31;
    const long base_row = (long)blockIdx.x * 8;

    {   // warp w layer-norms row base_row + w (CM = 64 = 2 per lane)
        const float* x = m + (base_row + warp) * CM;
        float a0 = x[lane], a1 = x[lane + 32];
        float s  = a0 + a1;
        float ss = a0 * a0 + a1 * a1;
        #pragma unroll
        for (int o = 16; o > 0; o >>= 1) {
            s  += __shfl_down_sync(0xffffffffu, s,  o);
            ss += __shfl_down_sync(0xffffffffu, ss, o);
        }
        float mu   = __shfl_sync(0xffffffffu, s, 0)  * (1.0f / 64.0f);
        float var  = __shfl_sync(0xffffffffu, ss, 0) * (1.0f / 64.0f) - mu * mu;
        float rstd = rsqrtf(var + 1e-5f);
        mn[warp][lane]      = (a0 - mu) * rstd * lw[lane]      + lb[lane];
        mn[warp][lane + 32] = (a1 - mu) * rstd * lw[lane + 32] + lb[lane + 32];
    }
    __syncthreads();

    float accv[8], accg[8];
    #pragma unroll
    for (int r = 0; r < 8; ++r) { accv[r] = 0.f; accg[r] = 0.f; }

    #pragma unroll 8
    for (int c = 0; c < CM; ++c) {
        float wv = Wm[c * HD + tid];
        float wg = Wg[c * HD + tid];
        #pragma unroll
        for (int r = 0; r < 8; ++r) {
            float t = mn[r][c];      // broadcast LDS
            accv[r] = fmaf(t, wv, accv[r]);
            accg[r] = fmaf(t, wg, accg[r]);
        }
    }
    #pragma unroll
    for (int r = 0; r < 8; ++r) {
        long idx = (base_row + r) * HD + tid;
        g_v[idx] = accv[r];
        g_g[idx] = 1.0f / (1.0f + __expf(-accg[r]));
    }
}

// ---------------------------------------------------------------------------
// K2 (rewritten): LayerNorm(z) fused with b[i,h,j] = zn@Wz.
// 32 rows per block: 8 warps x 4 rows, one warp per row (CZ=128 = 4/lane,
// float4). Wz transposed to [h][c] in smem -> conflict-free LDS.128 reads.
// Butterfly reductions; lanes 0..7 write the 8 head outputs.
// ---------------------------------------------------------------------------
__global__ void __launch_bounds__(256) k_ln_z_b(
    const float* __restrict__ z,
    const float* __restrict__ lw, const float* __restrict__ lb,
    const float* __restrict__ Wz)
{
    __shared__ float wzs[H][CZ];            // transposed: wzs[h][c]
    const int tid  = threadIdx.x;
    const int warp = tid >> 5, lane = tid & 31;

    #pragma unroll
    for (int k = tid; k < CZ * H; k += 256) {
        int c = k >> 3, h = k & 7;          // Wz[c][h] row-major
        wzs[h][c] = Wz[k];
    }
    __syncthreads();

    const int c0 = lane * 4;
    const float4 lwv = *(const float4*)&lw[c0];
    const float4 lbv = *(const float4*)&lb[c0];
    const long row0 = (long)blockIdx.x * 32;

    #pragma unroll
    for (int it = 0; it < 4; ++it) {
        const long row = row0 + warp + it * 8;      // i*T + j
        const float4 zv = *(const float4*)&z[row * CZ + c0];

        float s  = zv.x + zv.y + zv.z + zv.w;
        float ss = zv.x*zv.x + zv.y*zv.y + zv.z*zv.z + zv.w*zv.w;
        #pragma unroll
        for (int o = 16; o > 0; o >>= 1) {
            s  += __shfl_xor_sync(0xffffffffu, s,  o);
            ss += __shfl_xor_sync(0xffffffffu, ss, o);
        }
        float mu   = s * (1.0f / 128.0f);
        float rstd = rsqrtf(ss * (1.0f / 128.0f) - mu * mu + 1e-5f);

        float zn0 = (zv.x - mu) * rstd * lwv.x + lbv.x;
        float zn1 = (zv.y - mu) * rstd * lwv.y + lbv.y;
        float zn2 = (zv.z - mu) * rstd * lwv.z + lbv.z;
        float zn3 = (zv.w - mu) * rstd * lwv.w + lbv.w;

        float p[H];
        #pragma unroll
        for (int h = 0; h < H; ++h) {
            float4 wv = *(const float4*)&wzs[h][c0];
            p[h] = zn0*wv.x + zn1*wv.y + zn2*wv.z + zn3*wv.w;
        }
        #pragma unroll
        for (int o = 16; o > 0; o >>= 1) {
            #pragma unroll
            for (int h = 0; h < H; ++h)
                p[h] += __shfl_xor_sync(0xffffffffu, p[h], o);
        }
        if (lane < H) {
            long i = row >> 9, j = row & 511;
            g_w[i * (long)(H * T) + (long)lane * T + j] = p[lane];
        }
    }
}

// ---------------------------------------------------------------------------
// K3: softmax over j (contiguous, 512 elems). One block per (i,h).
// ---------------------------------------------------------------------------
__global__ void __launch_bounds__(256) k_softmax()
{
    float* p = g_w + (long)blockIdx.x * T;
    const int tid = threadIdx.x;
    __shared__ float red[8], red2[8];

    float a = p[tid], b = p[tid + 256];
    float mx = fmaxf(a, b);
    #pragma unroll
    for (int o = 16; o > 0; o >>= 1) mx = fmaxf(mx, __shfl_down_sync(0xffffffffu, mx, o));
    if ((tid & 31) == 0) red[tid >> 5] = mx;
    __syncthreads();
    float m8 = red[0];
    #pragma unroll
    for (int w = 1; w < 8; ++w) m8 = fmaxf(m8, red[w]);

    float e0 = __expf(a - m8), e1 = __expf(b - m8);
    float s = e0 + e1;
    #pragma unroll
    for (int o = 16; o > 0; o >>= 1) s += __shfl_down_sync(0xffffffffu, s, o);
    if ((tid & 31) == 0) red2[tid >> 5] = s;
    __syncthreads();
    float tot = red2[0];
    #pragma unroll
    for (int w = 1; w < 8; ++w) tot += red2[w];
    float inv = 1.0f / tot;
    p[tid]       = e0 * inv;
    p[tid + 256] = e1 * inv;
}

// ---------------------------------------------------------------------------
// K4 (dominant, 68.7 GF): per head h, C[i,n] = sum_j W[i,j] * V[j,n],
// n = s*32 + d (N=16384, M=512, K=512). 128x128x16 tiles, 8x8 per thread.
// Double-buffered smem: global loads for tile t+1 issued before compute of
// tile t, so LDG latency overlaps the 1024-FFMA mainloop body.
// Gate g applied in the epilogue; result to g_o[s][i][h*D+d].
// ---------------------------------------------------------------------------
#define MT 128
#define NT 128
#define KT 16
#define SMP 132   // padded row (multiple of 4 for float4 alignment)

__global__ void __launch_bounds__(256) k_wav()
{
    __shared__ float As[2][KT][SMP];   // As[buf][k][i_local] (transposed)
    __shared__ float Bs[2][KT][SMP];   // Bs[buf][k][n_local]

    const int h  = blockIdx.z;
    const int i0 = blockIdx.y * MT;
    const int n0 = blockIdx.x * NT;
    const int s_base = n0 >> 5;     // 4 s-values per block

    const int tid = threadIdx.x;
    const int tx = tid & 15;        // n direction
    const int ty = tid >> 4;        // i direction

    // A-load decode (2 float4s per thread)
    const int a_iloc0 = tid >> 2,         a_kc0 = tid & 3;
    const int a_iloc1 = (tid + 256) >> 2, a_kc1 = tid & 3;
    // B-load decode (2 float4s per thread)
    const int b_k0 = tid >> 5,           b_f0 = tid & 31;
    const int b_k1 = (tid + 256) >> 5,   b_f1 = tid & 31;

    const long wbase = (long)h * 512;   // g_w[i*4096 + h*512 + j]
    const long vbase = (long)h * 32;    // g_v[s*131072 + j*256 + h*32 + d]

    const float* aptr0 = &g_w[(long)(i0 + a_iloc0) * 4096 + wbase + a_kc0 * 4];
    const float* aptr1 = &g_w[(long)(i0 + a_iloc1) * 4096 + wbase + a_kc1 * 4];
    const float* bptr0 = &g_v[(long)(s_base + (b_f0 >> 3)) * 131072 + (long)b_k0 * 256 + vbase + (b_f0 & 7) * 4];
    const float* bptr1 = &g_v[(long)(s_base + (b_f1 >> 3)) * 131072 + (long)b_k1 * 256 + vbase + (b_f1 & 7) * 4];

    float acc[8][8];
    #pragma unroll
    for (int q = 0; q < 8; ++q)
        #pragma unroll
        for (int r = 0; r < 8; ++r) acc[q][r] = 0.f;

    // ---- prologue: load tile 0 into buffer 0
    float4 ra0 = *(const float4*)(aptr0);
    float4 ra1 = *(const float4*)(aptr1);
    float4 rb0 = *(const float4*)(bptr0);
    float4 rb1 = *(const float4*)(bptr1);
    {
        As[0][a_kc0*4+0][a_iloc0] = ra0.x; As[0][a_kc0*4+1][a_iloc0] = ra0.y;
        As[0][a_kc0*4+2][a_iloc0] = ra0.z; As[0][a_kc0*4+3][a_iloc0] = ra0.w;
        As[0][a_kc1*4+0][a_iloc1] = ra1.x; As[0][a_kc1*4+1][a_iloc1] = ra1.y;
        As[0][a_kc1*4+2][a_iloc1] = ra1.z; As[0][a_kc1*4+3][a_iloc1] = ra1.w;
        *(float4*)&Bs[0][b_k0][b_f0 * 4] = rb0;
        *(float4*)&Bs[0][b_k1][b_f1 * 4] = rb1;
    }
    __syncthreads();

    int buf = 0;
    for (int t = 0; t < 32; ++t) {               // 512 / KT tiles
        // ---- issue global loads for tile t+1 (into registers) early
        if (t < 31) {
            const long joff  = (long)(t + 1) * KT;
            ra0 = *(const float4*)(aptr0 + joff);
            ra1 = *(const float4*)(aptr1 + joff);
            rb0 = *(const float4*)(bptr0 + joff * 256);
            rb1 = *(const float4*)(bptr1 + joff * 256);
        }

        // ---- compute on buffer `buf`
        #pragma unroll
        for (int k = 0; k < KT; ++k) {
            float4 a0 = *(const float4*)&As[buf][k][ty * 8];
            float4 a1 = *(const float4*)&As[buf][k][ty * 8 + 4];
            float4 b0 = *(const float4*)&Bs[buf][k][tx * 8];
            float4 b1 = *(const float4*)&Bs[buf][k][tx * 8 + 4];
            float av[8] = {a0.x, a0.y, a0.z, a0.w, a1.x, a1.y, a1.z, a1.w};
            float bv[8] = {b0.x, b0.y, b0.z, b0.w, b1.x, b1.y, b1.z, b1.w};
            #pragma unroll
            for (int q = 0; q < 8; ++q)
                #pragma unroll
                for (int r = 0; r < 8; ++r)
                    acc[q][r] = fmaf(av[q], bv[r], acc[q][r]);
        }

        // ---- store tile t+1 into the other buffer
        if (t < 31) {
            int nb = buf ^ 1;
            __syncthreads();
            As[nb][a_kc0*4+0][a_iloc0] = ra0.x; As[nb][a_kc0*4+1][a_iloc0] = ra0.y;
            As[nb][a_kc0*4+2][a_iloc0] = ra0.z; As[nb][a_kc0*4+3][a_iloc0] = ra0.w;
            As[nb][a_kc1*4+0][a_iloc1] = ra1.x; As[nb][a_kc1*4+1][a_iloc1] = ra1.y;
            As[nb][a_kc1*4+2][a_iloc1] = ra1.z; As[nb][a_kc1*4+3][a_iloc1] = ra1.w;
            *(float4*)&Bs[nb][b_k0][b_f0 * 4] = rb0;
            *(float4*)&Bs[nb][b_k1][b_f1 * 4] = rb1;
            __syncthreads();
            buf = nb;
        }
    }

    // ---- epilogue: multiply by gate, store
    const int s_loc = (tx * 8) >> 5;
    const int d0    = (tx * 8) & 31;
    const long sb   = (long)(s_base + s_loc) * 131072 + (long)h * 32 + d0;
    #pragma unroll
    for (int q = 0; q < 8; ++q) {
        long off = sb + (long)(i0 + ty * 8 + q) * 256;
        float4 gg0 = *(const float4*)&g_g[off];
        float4 gg1 = *(const float4*)&g_g[off + 4];
        float4 o0 = make_float4(acc[q][0]*gg0.x, acc[q][1]*gg0.y, acc[q][2]*gg0.z, acc[q][3]*gg0.w);
        float4 o1 = make_float4(acc[q][4]*gg1.x, acc[q][5]*gg1.y, acc[q][6]*gg1.z, acc[q][7]*gg1.w);
        *(float4*)&g_o[off]     = o0;
        *(float4*)&g_o[off + 4] = o1;
    }
}

// ---------------------------------------------------------------------------
// K5: out[(s,i), c] = sum_k o[(s,i),k] * Wo[k,c].  16 rows/block, Wo via L1.
// ---------------------------------------------------------------------------
__global__ void __launch_bounds__(256) k_out(
    const float* __restrict__ Wo, float* __restrict__ out)
{
    __shared__ float sm[16][HD];
    const long row0 = (long)blockIdx.x * 16;
    const int tid = threadIdx.x;

    #pragma unroll
    for (int u = 0; u < 4; ++u) {
        int idx = tid + u * 256;            // float4 index
        int r = idx >> 6, k4 = idx & 63;
        *(float4*)&sm[r][k4 * 4] = *(const float4*)&g_o[(row0 + r) * HD + k4 * 4];
    }
    __syncthreads();

    const int c = tid & 63;
    const int q = tid >> 6;                 // rows q*4 .. q*4+3
    float acc[4] = {0.f, 0.f, 0.f, 0.f};
    #pragma unroll 8
    for (int k = 0; k < HD; ++k) {
        float wo = Wo[k * 64 + c];
        #pragma unroll
        for (int r = 0; r < 4; ++r)
            acc[r] = fmaf(sm[q * 4 + r][k], wo, acc[r]);
    }
    #pragma unroll
    for (int r = 0; r < 4; ++r)
        out[(row0 + q * 4 + r) * 64 + c] = acc[r];
}

// ---------------------------------------------------------------------------
extern "C" void kernel_launch(void* const* d_in, const int* in_sizes, int n_in,
                              void* d_out, int out_size)
{
    const float* m   = (const float*)d_in[0];
    const float* z   = (const float*)d_in[1];
    const float* nmw = (const float*)d_in[2];
    const float* nmb = (const float*)d_in[3];
    const float* nzw = (const float*)d_in[4];
    const float* nzb = (const float*)d_in[5];
    const float* Wm  = (const float*)d_in[6];
    const float* Wg  = (const float*)d_in[7];
    const float* Wz  = (const float*)d_in[8];
    const float* Wo  = (const float*)d_in[9];
    float* out = (float*)d_out;

    k_ln_m_vg<<<(S * T) / 8, 256>>>(m, nmw, nmb, Wm, Wg);
    k_ln_z_b<<<(T * T) / 32, 256>>>(z, nzw, nzb, Wz);
    k_softmax<<<T * H, 256>>>();
    dim3 gD(16384 / NT, T / MT, H);
    k_wav<<<gD, 256>>>();
    k_out<<<(S * T) / 16, 256>>>(Wo, out);
}

// round 13
// speedup vs baseline: 1.3836x; 1.3836x over previous
#include <cuda_runtime.h>
#include <cuda_fp16.h>
#include <math.h>
#include <cstdint>

#define S 512
#define T 512
#define CM 64
#define CZ 128
#define H 8
#define D 32
#define HD 256

// ---------------------------------------------------------------------------
// Scratch (device globals: allocation-free rule)
// ---------------------------------------------------------------------------
__device__ float g_g[(size_t)S*T*HD];            // gate [s][i][h*32+d] fp32
__device__ float g_w[(size_t)T*H*T];             // pair logits [i][h][j] fp32
__device__ float g_o[(size_t)S*T*HD];            // o [s][i][h*32+d] fp32
__device__ __half g_w_hi[(size_t)T*H*T];         // softmax(w) split hi [i][h][j]
__device__ __half g_w_lo[(size_t)T*H*T];         // softmax(w) split lo
__device__ __half g_vT_hi[(size_t)H*16384*512];  // V^T split hi [h][s*32+d][j]
__device__ __half g_vT_lo[(size_t)H*16384*512];  // V^T split lo

// ---------------------------------------------------------------------------
// sm_80-level PTX helpers (compile on plain .target sm_103)
// ---------------------------------------------------------------------------
__device__ __forceinline__ uint32_t smem_u32(const void* p) {
    uint32_t a;
    asm("{ .reg .u64 t; cvta.to.shared.u64 t, %1; cvt.u32.u64 %0, t; }" : "=r"(a) : "l"(p));
    return a;
}
__device__ __forceinline__ void cp16(uint32_t smem, const void* gmem) {
    asm volatile("cp.async.cg.shared.global [%0], [%1], 16;" :: "r"(smem), "l"(gmem));
}
#define CP_COMMIT() asm volatile("cp.async.commit_group;" ::: "memory")
#define CP_WAIT1()  asm volatile("cp.async.wait_group 1;" ::: "memory")
#define CP_WAIT0()  asm volatile("cp.async.wait_group 0;" ::: "memory")

#define LDSM4(r0, r1, r2, r3, addr) \
    asm volatile("ldmatrix.sync.aligned.m8n8.x4.shared.b16 {%0,%1,%2,%3}, [%4];" \
                 : "=r"(r0), "=r"(r1), "=r"(r2), "=r"(r3) : "r"(addr))

__device__ __forceinline__ void mma16816(float c[4], const uint32_t a[4], const uint32_t b[2]) {
    asm volatile(
        "mma.sync.aligned.m16n8k16.row.col.f32.f16.f16.f32 "
        "{%0,%1,%2,%3}, {%4,%5,%6,%7}, {%8,%9}, {%0,%1,%2,%3};"
        : "+f"(c[0]), "+f"(c[1]), "+f"(c[2]), "+f"(c[3])
        : "r"(a[0]), "r"(a[1]), "r"(a[2]), "r"(a[3]), "r"(b[0]), "r"(b[1]));
}

// ---------------------------------------------------------------------------
// K1: LayerNorm(m) fused with v = mn@Wm (transposed + fp16-split to
// g_vT[h][s*32+d][j]) and g = sigmoid(mn@Wg) (fp32 gate).
// ---------------------------------------------------------------------------
__global__ void __launch_bounds__(256) k_ln_m_vg(
    const float* __restrict__ m,
    const float* __restrict__ lw, const float* __restrict__ lb,
    const float* __restrict__ Wm, const float* __restrict__ Wg)
{
    __shared__ float mn[8][CM];
    const int tid  = threadIdx.x;
    const int warp = tid >> 5, lane = tid & 31;
    const long base_row = (long)blockIdx.x * 8;

    {
        const float* x = m + (base_row + warp) * CM;
        float a0 = x[lane], a1 = x[lane + 32];
        float s  = a0 + a1;
        float ss = a0 * a0 + a1 * a1;
        #pragma unroll
        for (int o = 16; o > 0; o >>= 1) {
            s  += __shfl_down_sync(0xffffffffu, s,  o);
            ss += __shfl_down_sync(0xffffffffu, ss, o);
        }
        float mu   = __shfl_sync(0xffffffffu, s, 0)  * (1.0f / 64.0f);
        float var  = __shfl_sync(0xffffffffu, ss, 0) * (1.0f / 64.0f) - mu * mu;
        float rstd = rsqrtf(var + 1e-5f);
        mn[warp][lane]      = (a0 - mu) * rstd * lw[lane]      + lb[lane];
        mn[warp][lane + 32] = (a1 - mu) * rstd * lw[lane + 32] + lb[lane + 32];
    }
    __syncthreads();

    float accv[8], accg[8];
    #pragma unroll
    for (int r = 0; r < 8; ++r) { accv[r] = 0.f; accg[r] = 0.f; }

    #pragma unroll 8
    for (int c = 0; c < CM; ++c) {
        float wv = Wm[c * HD + tid];
        float wg = Wg[c * HD + tid];
        #pragma unroll
        for (int r = 0; r < 8; ++r) {
            float t = mn[r][c];
            accv[r] = fmaf(t, wv, accv[r]);
            accg[r] = fmaf(t, wg, accg[r]);
        }
    }

    #pragma unroll
    for (int r = 0; r < 8; ++r) {
        long idx = (base_row + r) * HD + tid;
        g_g[idx] = 1.0f / (1.0f + __expf(-accg[r]));
    }

    // v -> transposed, fp16 hi/lo split (8 consecutive j per thread = one uint4)
    const int h = tid >> 5, d = tid & 31;
    const long sidx = base_row >> 9;
    const long j0   = base_row & 511;
    union { uint4 u; __half b[8]; } ph, pl;
    #pragma unroll
    for (int r = 0; r < 8; ++r) {
        __half hv = __float2half_rn(accv[r]);
        float rem = accv[r] - __half2float(hv);
        ph.b[r] = hv;
        pl.b[r] = __float2half_rn(rem);
    }
    const size_t off = (size_t)h * (16384u * 512u) + ((size_t)sidx * 32 + d) * 512 + j0;
    *(uint4*)(g_vT_hi + off) = ph.u;
    *(uint4*)(g_vT_lo + off) = pl.u;
}

// ---------------------------------------------------------------------------
// K2: LayerNorm(z) fused with b[i,h,j] = zn@Wz.
// ---------------------------------------------------------------------------
__global__ void __launch_bounds__(256) k_ln_z_b(
    const float* __restrict__ z,
    const float* __restrict__ lw, const float* __restrict__ lb,
    const float* __restrict__ Wz)
{
    __shared__ float wzs[H][CZ];
    const int tid  = threadIdx.x;
    const int warp = tid >> 5, lane = tid & 31;

    #pragma unroll
    for (int k = tid; k < CZ * H; k += 256) {
        int c = k >> 3, h = k & 7;
        wzs[h][c] = Wz[k];
    }
    __syncthreads();

    const int c0 = lane * 4;
    const float4 lwv = *(const float4*)&lw[c0];
    const float4 lbv = *(const float4*)&lb[c0];
    const long row0 = (long)blockIdx.x * 32;

    #pragma unroll
    for (int it = 0; it < 4; ++it) {
        const long row = row0 + warp + it * 8;
        const float4 zv = *(const float4*)&z[row * CZ + c0];

        float s  = zv.x + zv.y + zv.z + zv.w;
        float ss = zv.x*zv.x + zv.y*zv.y + zv.z*zv.z + zv.w*zv.w;
        #pragma unroll
        for (int o = 16; o > 0; o >>= 1) {
            s  += __shfl_xor_sync(0xffffffffu, s,  o);
            ss += __shfl_xor_sync(0xffffffffu, ss, o);
        }
        float mu   = s * (1.0f / 128.0f);
        float rstd = rsqrtf(ss * (1.0f / 128.0f) - mu * mu + 1e-5f);

        float zn0 = (zv.x - mu) * rstd * lwv.x + lbv.x;
        float zn1 = (zv.y - mu) * rstd * lwv.y + lbv.y;
        float zn2 = (zv.z - mu) * rstd * lwv.z + lbv.z;
        float zn3 = (zv.w - mu) * rstd * lwv.w + lbv.w;

        float p[H];
        #pragma unroll
        for (int h = 0; h < H; ++h) {
            float4 wv = *(const float4*)&wzs[h][c0];
            p[h] = zn0*wv.x + zn1*wv.y + zn2*wv.z + zn3*wv.w;
        }
        #pragma unroll
        for (int o = 16; o > 0; o >>= 1) {
            #pragma unroll
            for (int h = 0; h < H; ++h)
                p[h] += __shfl_xor_sync(0xffffffffu, p[h], o);
        }
        if (lane < H) {
            long i = row >> 9, j = row & 511;
            g_w[i * (long)(H * T) + (long)lane * T + j] = p[lane];
        }
    }
}

// ---------------------------------------------------------------------------
// K3: softmax over j, output fp16 hi/lo split (MMA A operand).
// ---------------------------------------------------------------------------
__global__ void __launch_bounds__(256) k_softmax()
{
    const long rb = (long)blockIdx.x * T;
    const float* p = g_w + rb;
    const int tid = threadIdx.x;
    __shared__ float red[8], red2[8];

    float a = p[tid], b = p[tid + 256];
    float mx = fmaxf(a, b);
    #pragma unroll
    for (int o = 16; o > 0; o >>= 1) mx = fmaxf(mx, __shfl_down_sync(0xffffffffu, mx, o));
    if ((tid & 31) == 0) red[tid >> 5] = mx;
    __syncthreads();
    float m8 = red[0];
    #pragma unroll
    for (int w = 1; w < 8; ++w) m8 = fmaxf(m8, red[w]);

    float e0 = __expf(a - m8), e1 = __expf(b - m8);
    float s = e0 + e1;
    #pragma unroll
    for (int o = 16; o > 0; o >>= 1) s += __shfl_down_sync(0xffffffffu, s, o);
    if ((tid & 31) == 0) red2[tid >> 5] = s;
    __syncthreads();
    float tot = red2[0];
    #pragma unroll
    for (int w = 1; w < 8; ++w) tot += red2[w];
    float inv = 1.0f / tot;

    float w0 = e0 * inv, w1 = e1 * inv;
    __half h0 = __float2half_rn(w0);
    __half h1 = __float2half_rn(w1);
    g_w_hi[rb + tid]       = h0;
    g_w_hi[rb + tid + 256] = h1;
    g_w_lo[rb + tid]       = __float2half_rn(w0 - __half2float(h0));
    g_w_lo[rb + tid + 256] = __float2half_rn(w1 - __half2float(h1));
}

// ---------------------------------------------------------------------------
// K4: tensor-core via mma.sync (HMMA.16816). Per (h, i-tile 128, n-tile 128):
//   C[i,n] = sum_j W[i,j]*VT[n,j],  3-term fp16 split for fp32-level accuracy.
// 8 warps (2M x 4N), warp tile 64x32, KC=64, cp.async double buffer,
// padded smem stride 144B (conflict-free ldmatrix). Gate in epilogue.
// ---------------------------------------------------------------------------
#define MAT_BYTES 18432                 // 128 rows * 144B
#define STG 73728                       // 4 matrices per stage
#define SM_TOTAL (2 * STG)              // 147456

__device__ __forceinline__ void load_stage(uint32_t sm,
    const char* Ahi, const char* Alo, const char* Bhi, const char* Blo, int tid)
{
    #pragma unroll
    for (int q = 0; q < 4; ++q) {
        int idx = tid + q * 256;            // 0..1023
        int r = idx >> 3, c16 = (idx & 7) * 16;
        uint32_t so = sm + r * 144 + c16;
        cp16(so,                 Ahi + (size_t)r * 8192 + c16);
        cp16(so + MAT_BYTES,     Alo + (size_t)r * 8192 + c16);
        cp16(so + 2 * MAT_BYTES, Bhi + (size_t)r * 1024 + c16);
        cp16(so + 3 * MAT_BYTES, Blo + (size_t)r * 1024 + c16);
    }
}

__global__ void __launch_bounds__(256, 1) k_wav_mma()
{
    extern __shared__ char smem[];
    const uint32_t sm_base = smem_u32(smem);
    const int tid = threadIdx.x;
    const int wid = tid >> 5, lane = tid & 31;
    const int warpM = wid >> 2, warpN = wid & 3;

    const int h  = blockIdx.z;
    const int i0 = blockIdx.y * 128;
    const int n0 = blockIdx.x * 128;

    const char* srcAhi = (const char*)g_w_hi  + ((size_t)i0 * 4096 + (size_t)h * 512) * 2;
    const char* srcAlo = (const char*)g_w_lo  + ((size_t)i0 * 4096 + (size_t)h * 512) * 2;
    const char* srcBhi = (const char*)g_vT_hi + ((size_t)h * 16384 * 512 + (size_t)n0 * 512) * 2;
    const char* srcBlo = (const char*)g_vT_lo + ((size_t)h * 16384 * 512 + (size_t)n0 * 512) * 2;

    float acc[4][4][4];
    #pragma unroll
    for (int mi = 0; mi < 4; ++mi)
        #pragma unroll
        for (int ni = 0; ni < 4; ++ni)
            #pragma unroll
            for (int e = 0; e < 4; ++e) acc[mi][ni][e] = 0.f;

    // prologue: chunk 0 -> stage 0
    load_stage(sm_base, srcAhi, srcAlo, srcBhi, srcBlo, tid);
    CP_COMMIT();

    for (int c = 0; c < 8; ++c) {
        if (c < 7) {
            const size_t off = (size_t)(c + 1) * 128;   // 64 halfs per chunk
            load_stage(sm_base + ((c + 1) & 1) * STG,
                       srcAhi + off, srcAlo + off, srcBhi + off, srcBlo + off, tid);
            CP_COMMIT();
            CP_WAIT1();
        } else {
            CP_WAIT0();
        }
        __syncthreads();

        const uint32_t st = sm_base + (c & 1) * STG;
        #pragma unroll
        for (int ks = 0; ks < 4; ++ks) {
            uint32_t ahi[4][4], alo[4][4], bhi[4][2], blo[4][2];
            const int acol = (ks * 16 + ((lane >> 4) << 3)) * 2;
            const int arow = lane & 15;
            #pragma unroll
            for (int mi = 0; mi < 4; ++mi) {
                uint32_t ad = st + (warpM * 64 + mi * 16 + arow) * 144 + acol;
                LDSM4(ahi[mi][0], ahi[mi][1], ahi[mi][2], ahi[mi][3], ad);
                LDSM4(alo[mi][0], alo[mi][1], alo[mi][2], alo[mi][3], ad + MAT_BYTES);
            }
            const int brow = (lane & 7) + ((lane >> 4) << 3);
            const int bcol = (ks * 16 + (((lane >> 3) & 1) << 3)) * 2;
            #pragma unroll
            for (int bi = 0; bi < 2; ++bi) {
                uint32_t bd = st + 2 * MAT_BYTES + (warpN * 32 + bi * 16 + brow) * 144 + bcol;
                uint32_t r0, r1, r2, r3;
                LDSM4(r0, r1, r2, r3, bd);
                bhi[bi*2][0] = r0; bhi[bi*2][1] = r1; bhi[bi*2+1][0] = r2; bhi[bi*2+1][1] = r3;
                LDSM4(r0, r1, r2, r3, bd + MAT_BYTES);
                blo[bi*2][0] = r0; blo[bi*2][1] = r1; blo[bi*2+1][0] = r2; blo[bi*2+1][1] = r3;
            }
            #pragma unroll
            for (int mi = 0; mi < 4; ++mi)
                #pragma unroll
                for (int ni = 0; ni < 4; ++ni) {
                    mma16816(acc[mi][ni], ahi[mi], bhi[ni]);
                    mma16816(acc[mi][ni], alo[mi], bhi[ni]);
                    mma16816(acc[mi][ni], ahi[mi], blo[ni]);
                }
        }
        __syncthreads();
    }

    // epilogue: gate + store. C frag: c0,c1 = (row, col..col+1); c2,c3 = row+8.
    const int r  = lane >> 2;
    const int cc = (lane & 3) * 2;
    #pragma unroll
    for (int mi = 0; mi < 4; ++mi) {
        const int irow = i0 + warpM * 64 + mi * 16 + r;
        #pragma unroll
        for (int ni = 0; ni < 4; ++ni) {
            const int n = n0 + warpN * 32 + ni * 8 + cc;
            const int s = n >> 5, d = n & 31;
            const size_t o1 = (size_t)s * 131072 + (size_t)irow * 256 + h * 32 + d;
            const size_t o2 = o1 + 8 * 256;
            float2 g1 = *(const float2*)&g_g[o1];
            float2 g2 = *(const float2*)&g_g[o2];
            float2 v1 = make_float2(acc[mi][ni][0] * g1.x, acc[mi][ni][1] * g1.y);
            float2 v2 = make_float2(acc[mi][ni][2] * g2.x, acc[mi][ni][3] * g2.y);
            *(float2*)&g_o[o1] = v1;
            *(float2*)&g_o[o2] = v2;
        }
    }
}

// ---------------------------------------------------------------------------
// K5: out[(s,i), c] = sum_k o[(s,i),k] * Wo[k,c].
// ---------------------------------------------------------------------------
__global__ void __launch_bounds__(256) k_out(
    const float* __restrict__ Wo, float* __restrict__ out)
{
    __shared__ float sm[16][HD];
    const long row0 = (long)blockIdx.x * 16;
    const int tid = threadIdx.x;

    #pragma unroll
    for (int u = 0; u < 4; ++u) {
        int idx = tid + u * 256;
        int r = idx >> 6, k4 = idx & 63;
        *(float4*)&sm[r][k4 * 4] = *(const float4*)&g_o[(row0 + r) * HD + k4 * 4];
    }
    __syncthreads();

    const int c = tid & 63;
    const int q = tid >> 6;
    float acc[4] = {0.f, 0.f, 0.f, 0.f};
    #pragma unroll 8
    for (int k = 0; k < HD; ++k) {
        float wo = Wo[k * 64 + c];
        #pragma unroll
        for (int r = 0; r < 4; ++r)
            acc[r] = fmaf(sm[q * 4 + r][k], wo, acc[r]);
    }
    #pragma unroll
    for (int r = 0; r < 4; ++r)
        out[(row0 + q * 4 + r) * 64 + c] = acc[r];
}

// ---------------------------------------------------------------------------
extern "C" void kernel_launch(void* const* d_in, const int* in_sizes, int n_in,
                              void* d_out, int out_size)
{
    const float* m   = (const float*)d_in[0];
    const float* z   = (const float*)d_in[1];
    const float* nmw = (const float*)d_in[2];
    const float* nmb = (const float*)d_in[3];
    const float* nzw = (const float*)d_in[4];
    const float* nzb = (const float*)d_in[5];
    const float* Wm  = (const float*)d_in[6];
    const float* Wg  = (const float*)d_in[7];
    const float* Wz  = (const float*)d_in[8];
    const float* Wo  = (const float*)d_in[9];
    float* out = (float*)d_out;

    cudaFuncSetAttribute(k_wav_mma, cudaFuncAttributeMaxDynamicSharedMemorySize, SM_TOTAL);

    k_ln_m_vg<<<(S * T) / 8, 256>>>(m, nmw, nmb, Wm, Wg);
    k_ln_z_b<<<(T * T) / 32, 256>>>(z, nzw, nzb, Wz);
    k_softmax<<<T * H, 256>>>();
    dim3 gD(128, 4, H);
    k_wav_mma<<<gD, 256, SM_TOTAL>>>();
    k_out<<<(S * T) / 16, 256>>>(Wo, out);
}